// round 14
// baseline (speedup 1.0000x reference)
#include <cuda_runtime.h>
#include <cuda_fp16.h>
#include <cstdint>

// Problem dims (fixed)
#define BB 4
#define TT 4096
#define HH 2048
#define LL 4
#define MROWS 16384
#define N3H 6144
#define KDIM 2048

// GEMM tiling: CTA 128x128, BK=32 (64B rows), 3-stage cp.async, 8 warps (4x2),
// warp 32x64, single pass (A fp16, B fp16), fp32 accum.
#define ROWB  64
#define KCH   2
#define NITER (KDIM / 32)             // 64
#define TILEB (128 * ROWB)            // 8 KB
#define STG_B (2 * TILEB)             // A + B = 16 KB
#define NSTAGE 3                      // 48 KB static

// ---------------- scratch (__device__ globals; referenced ONLY in device code)
__device__ __half g_BCh[(size_t)MROWS * N3H];     // 192 MB fp16
__device__ __half g_xh[(size_t)MROWS * HH];
__device__ __half g_yh[(size_t)MROWS * HH];
__device__ __half g_Wint_h[(size_t)N3H * HH];     // W_in^T  [6144][2048] fp16
__device__ __half g_Wot_h[(size_t)HH * HH];       // W_out^T [2048][2048] fp16

// ---------------- PTX helpers (plain sm_103-safe) ----------------------------
__device__ __forceinline__ uint32_t smem_u32(const void* p) {
    uint32_t a;
    asm("{ .reg .u64 t; cvta.to.shared.u64 t, %1; cvt.u32.u64 %0, t; }" : "=r"(a) : "l"(p));
    return a;
}
// 64B-row swizzle: conflict-free for 8-row ldmatrix groups
#define SWZ64(off) ((off) ^ (((off) >> 3) & 0x30))

#define CP_ASYNC16(dst, src) \
    asm volatile("cp.async.cg.shared.global [%0], [%1], 16;" :: "r"(dst), "l"(src))
#define CP_ASYNC_COMMIT() asm volatile("cp.async.commit_group;")
#define CP_ASYNC_WAIT(n)  asm volatile("cp.async.wait_group %0;" :: "n"(n))

#define LDSM_X4(r0, r1, r2, r3, addr) \
    asm volatile("ldmatrix.sync.aligned.m8n8.x4.shared.b16 {%0,%1,%2,%3}, [%4];" \
        : "=r"(r0), "=r"(r1), "=r"(r2), "=r"(r3) : "r"(addr))

// NOT volatile: pure register computation; ptxas may schedule freely.
#define MMA16816(d, a, b0, b1) \
    asm("mma.sync.aligned.m16n8k16.row.col.f32.f16.f16.f32 " \
        "{%0,%1,%2,%3}, {%4,%5,%6,%7}, {%8,%9}, {%0,%1,%2,%3};" \
        : "+f"((d)[0]), "+f"((d)[1]), "+f"((d)[2]), "+f"((d)[3]) \
        : "r"((a)[0]), "r"((a)[1]), "r"((a)[2]), "r"((a)[3]), "r"(b0), "r"(b1))

// ---------------- prep kernels ----------------------------------------------
__global__ __launch_bounds__(256)
void convert_x_kernel(const float* __restrict__ x)
{
    size_t i = ((size_t)blockIdx.x * 256 + threadIdx.x) * 4;
    float4 v = *(const float4*)(x + i);
    __half h[4] = {__float2half(v.x), __float2half(v.y),
                   __float2half(v.z), __float2half(v.w)};
    *(uint2*)(g_xh + i) = *(uint2*)h;
}

// transpose: in fp32 [R][C] -> (device-global) fp16 [C][R]
__global__ __launch_bounds__(256)
void transpose_h_kernel(const float* __restrict__ in, int wsel, int R, int C)
{
    __half* __restrict__ oh = wsel ? g_Wot_h : g_Wint_h;

    __shared__ float tile[32][33];
    int tx = threadIdx.x, ty = threadIdx.y;
    int x = blockIdx.x * 32 + tx;
    int y0 = blockIdx.y * 32;
    #pragma unroll
    for (int j = ty; j < 32; j += 8)
        tile[j][tx] = in[(size_t)(y0 + j) * C + x];
    __syncthreads();
    int ox = y0 + tx;
    int oy0 = blockIdx.x * 32;
    #pragma unroll
    for (int j = ty; j < 32; j += 8)
        oh[(size_t)(oy0 + j) * R + ox] = __float2half(tile[tx][j]);
}

// ---------------- single-pass fp16 mma.sync GEMM -----------------------------
// GSEL 0: C = g_BCh (fp16, Cw=N3H) = g_xh @ g_Wint_h^T
// GSEL 1: C = Cout  (fp32, Cw=HH)  = g_yh @ g_Wot_h^T
template<int GSEL>
__global__ __launch_bounds__(256, 2)
void gemm_mma_kernel(float* __restrict__ Cout)
{
    const __half* __restrict__ A = GSEL ? g_yh : g_xh;
    const __half* __restrict__ B = GSEL ? g_Wot_h : g_Wint_h;
    const int Cw = GSEL ? HH : N3H;

    __shared__ __align__(1024) char smem[NSTAGE * STG_B];
    const int tid = threadIdx.x;
    const int wid = tid >> 5;
    const int lid = tid & 31;
    const int wm = wid & 3;           // 4 warps in M -> 32 rows each
    const int wn = wid >> 2;          // 2 warps in N -> 64 cols each
    const int bm = blockIdx.y * 128;
    const int bn = blockIdx.x * 128;

    float acc[2][8][4];
    #pragma unroll
    for (int t = 0; t < 2; ++t)
        #pragma unroll
        for (int j = 0; j < 8; ++j)
            #pragma unroll
            for (int e = 0; e < 4; ++e) acc[t][j][e] = 0.f;

    const int a_row = (lid & 15);
    const int a_kb  = (lid & 16) ? 16 : 0;
    const int b_row = (lid & 7) + ((lid & 16) ? 8 : 0);
    const int b_kb  = (lid & 8) ? 16 : 0;

    // loader: one stage = A tile + B tile, 128 rows x 4 chunks each -> 4/thread
    auto load_stage = [&](char* sbase, int k0) {
        #pragma unroll
        for (int j = 0; j < 4; ++j) {
            int c   = tid + j * 256;       // 0..1023
            int sub = c >> 9;              // 0 = A, 1 = B
            int cc  = c & 511;
            int r   = cc >> 2, ch = cc & 3;
            const int rowbase = sub ? bn : bm;
            const __half* src = (sub ? B : A)
                                + (size_t)(rowbase + r) * KDIM + k0 + ch * 8;
            uint32_t dst = smem_u32(sbase + sub * TILEB);
            CP_ASYNC16(dst + SWZ64(r * ROWB + ch * 16), src);
        }
        CP_ASYNC_COMMIT();
    };

    // prologue: 2 stages in flight
    load_stage(smem,         0);
    load_stage(smem + STG_B, 32);

    int cur = 0;
    for (int i = 0; i < NITER; ++i) {
        if (i + 1 < NITER) { CP_ASYNC_WAIT(1); } else { CP_ASYNC_WAIT(0); }
        __syncthreads();

        char* sbase = smem + cur * STG_B;
        const uint32_t tA = smem_u32(sbase);
        const uint32_t tB = tA + TILEB;

        #pragma unroll
        for (int kk = 0; kk < KCH; ++kk) {
            const int kb = kk * 32;
            uint32_t av[2][4], bv[4][4];
            #pragma unroll
            for (int t = 0; t < 2; ++t) {
                int row = wm * 32 + t * 16 + a_row;
                LDSM_X4(av[t][0], av[t][1], av[t][2], av[t][3],
                        tA + SWZ64(row * ROWB + kb + a_kb));
            }
            #pragma unroll
            for (int g = 0; g < 4; ++g) {
                int row = wn * 64 + g * 16 + b_row;
                LDSM_X4(bv[g][0], bv[g][1], bv[g][2], bv[g][3],
                        tB + SWZ64(row * ROWB + kb + b_kb));
            }
            #pragma unroll
            for (int t = 0; t < 2; ++t)
                #pragma unroll
                for (int g = 0; g < 4; ++g) {
                    MMA16816(acc[t][2 * g],     av[t], bv[g][0], bv[g][1]);
                    MMA16816(acc[t][2 * g + 1], av[t], bv[g][2], bv[g][3]);
                }
        }

        if (i + 2 < NITER) {
            int nxt = cur + 2; if (nxt >= NSTAGE) nxt -= NSTAGE;
            load_stage(smem + nxt * STG_B, (i + 2) * 32);
        }
        if (++cur == NSTAGE) cur = 0;
    }

    // epilogue
    const int r0 = bm + wm * 32 + (lid >> 2);
    const int cb = bn + wn * 64 + (lid & 3) * 2;
    if (GSEL == 0) {
        // fp16 output to g_BCh
        #pragma unroll
        for (int t = 0; t < 2; ++t)
            #pragma unroll
            for (int j = 0; j < 8; ++j) {
                __half2 v0 = __floats2half2_rn(acc[t][j][0], acc[t][j][1]);
                __half2 v1 = __floats2half2_rn(acc[t][j][2], acc[t][j][3]);
                *(__half2*)(g_BCh + (size_t)(r0 + t * 16)     * N3H + cb + j * 8) = v0;
                *(__half2*)(g_BCh + (size_t)(r0 + t * 16 + 8) * N3H + cb + j * 8) = v1;
            }
    } else {
        #pragma unroll
        for (int t = 0; t < 2; ++t)
            #pragma unroll
            for (int j = 0; j < 8; ++j) {
                float2 v0 = make_float2(acc[t][j][0], acc[t][j][1]);
                float2 v1 = make_float2(acc[t][j][2], acc[t][j][3]);
                *(float2*)(Cout + (size_t)(r0 + t * 16)     * Cw + cb + j * 8) = v0;
                *(float2*)(Cout + (size_t)(r0 + t * 16 + 8) * Cw + cb + j * 8) = v1;
            }
    }
}

// ---------------- fused gate + mask + causal conv + Cg gate (fp16 in/out) ---
// 2 h per thread via __half2; fp32 arithmetic.
#define CONV_CHUNK 128

__global__ __launch_bounds__(256)
void conv_kernel(const int* __restrict__ mask, const float* __restrict__ conv_w)
{
    const int h2 = (blockIdx.x * 256 + threadIdx.x) * 2;   // even h
    const int b  = blockIdx.z;
    const int t0 = blockIdx.y * CONV_CHUNK;

    float2 cw[LL];
    #pragma unroll
    for (int k = 0; k < LL; ++k) {
        cw[k].x = conv_w[h2 * LL + k];
        cw[k].y = conv_w[(h2 + 1) * LL + k];
    }

    float2 p1 = {0.f, 0.f}, p2 = {0.f, 0.f}, p3 = {0.f, 0.f};
    #pragma unroll
    for (int d = 3; d >= 1; --d) {
        int t = t0 - d;
        float2 bx = {0.f, 0.f};
        if (t >= 0 && mask[b * TT + t] != 0) {
            size_t base = ((size_t)(b * TT + t)) * N3H;
            float2 Bg = __half22float2(*(const __half2*)(g_BCh + base + h2));
            float2 xg = __half22float2(*(const __half2*)(g_BCh + base + 2 * HH + h2));
            bx.x = Bg.x * xg.x; bx.y = Bg.y * xg.y;
        }
        p3 = p2; p2 = p1; p1 = bx;
    }

    for (int t = t0; t < t0 + CONV_CHUNK; ++t) {
        size_t base = ((size_t)(b * TT + t)) * N3H;
        float2 Bg = __half22float2(*(const __half2*)(g_BCh + base + h2));
        float2 Cg = __half22float2(*(const __half2*)(g_BCh + base + HH + h2));
        float2 xg = __half22float2(*(const __half2*)(g_BCh + base + 2 * HH + h2));
        bool m = (mask[b * TT + t] != 0);
        float2 bx;
        bx.x = m ? (Bg.x * xg.x) : 0.f;
        bx.y = m ? (Bg.y * xg.y) : 0.f;
        float2 conv;
        conv.x = cw[0].x * p3.x + cw[1].x * p2.x + cw[2].x * p1.x + cw[3].x * bx.x;
        conv.y = cw[0].y * p3.y + cw[1].y * p2.y + cw[2].y * p1.y + cw[3].y * bx.y;
        float2 y = {Cg.x * conv.x, Cg.y * conv.y};
        *(__half2*)(g_yh + ((size_t)(b * TT + t)) * HH + h2) = __floats2half2_rn(y.x, y.y);
        p3 = p2; p2 = p1; p1 = bx;
    }
}

// ---------------- launch -----------------------------------------------------
extern "C" void kernel_launch(void* const* d_in, const int* in_sizes, int n_in,
                              void* d_out, int out_size)
{
    const float* x      = (const float*)d_in[0];
    const int*   mask   = (const int*)d_in[1];    // bool widened to int32
    const float* W_in   = (const float*)d_in[2];
    const float* conv_w = (const float*)d_in[3];
    const float* W_out  = (const float*)d_in[4];
    float*       out    = (float*)d_out;

    // prep: convert x to fp16, transpose weights to fp16
    convert_x_kernel<<<(size_t)MROWS * HH / (256 * 4), 256>>>(x);
    transpose_h_kernel<<<dim3(N3H / 32, HH / 32), dim3(32, 8)>>>(W_in, 0, HH, N3H);
    transpose_h_kernel<<<dim3(HH / 32, HH / 32), dim3(32, 8)>>>(W_out, 1, HH, HH);

    // GEMM1: BCh = x @ W_in   (16384x2048 @ 2048x6144), fp16 out
    gemm_mma_kernel<0><<<dim3(N3H / 128, MROWS / 128), 256>>>(nullptr);

    // gate + conv + gate -> y (fp16)
    conv_kernel<<<dim3(HH / 512, TT / CONV_CHUNK, BB), 256>>>(mask, conv_w);

    // GEMM2: out = y @ W_out  (16384x2048 @ 2048x2048), fp32 out
    gemm_mma_kernel<1><<<dim3(HH / 128, MROWS / 128), 256>>>(out);
}

// round 15
// speedup vs baseline: 1.0477x; 1.0477x over previous
#include <cuda_runtime.h>
#include <cuda_fp16.h>
#include <cstdint>

// Problem dims (fixed)
#define BB 4
#define TT 4096
#define HH 2048
#define LL 4
#define MROWS 16384
#define N3H 6144
#define KDIM 2048

// GEMM tiling: CTA 128x128, BK=32 (64B rows), 3-stage cp.async, 8 warps (4x2),
// warp 32x64, single pass (A fp16, B fp16), fp32 accum.
#define ROWB  64
#define KCH   2
#define NITER (KDIM / 32)             // 64
#define TILEB (128 * ROWB)            // 8 KB
#define STG_B (2 * TILEB)             // A + B = 16 KB
#define NSTAGE 3                      // 48 KB static

// ---------------- scratch (__device__ globals; referenced ONLY in device code)
__device__ float  g_BCx[(size_t)MROWS * N3H];     // 384 MB fp32
__device__ __half g_xh[(size_t)MROWS * HH];
__device__ __half g_yh[(size_t)MROWS * HH];
__device__ __half g_Wint_h[(size_t)N3H * HH];     // W_in^T  [6144][2048] fp16
__device__ __half g_Wot_h[(size_t)HH * HH];       // W_out^T [2048][2048] fp16

// ---------------- PTX helpers (plain sm_103-safe) ----------------------------
__device__ __forceinline__ uint32_t smem_u32(const void* p) {
    uint32_t a;
    asm("{ .reg .u64 t; cvta.to.shared.u64 t, %1; cvt.u32.u64 %0, t; }" : "=r"(a) : "l"(p));
    return a;
}
// 64B-row swizzle: conflict-free for 8-row ldmatrix groups
#define SWZ64(off) ((off) ^ (((off) >> 3) & 0x30))

#define CP_ASYNC16(dst, src) \
    asm volatile("cp.async.cg.shared.global [%0], [%1], 16;" :: "r"(dst), "l"(src))
#define CP_ASYNC_COMMIT() asm volatile("cp.async.commit_group;")
#define CP_ASYNC_WAIT(n)  asm volatile("cp.async.wait_group %0;" :: "n"(n))

#define LDSM_X4(r0, r1, r2, r3, addr) \
    asm volatile("ldmatrix.sync.aligned.m8n8.x4.shared.b16 {%0,%1,%2,%3}, [%4];" \
        : "=r"(r0), "=r"(r1), "=r"(r2), "=r"(r3) : "r"(addr))

// NOT volatile: pure register computation; ptxas may schedule freely.
#define MMA16816(d, a, b0, b1) \
    asm("mma.sync.aligned.m16n8k16.row.col.f32.f16.f16.f32 " \
        "{%0,%1,%2,%3}, {%4,%5,%6,%7}, {%8,%9}, {%0,%1,%2,%3};" \
        : "+f"((d)[0]), "+f"((d)[1]), "+f"((d)[2]), "+f"((d)[3]) \
        : "r"((a)[0]), "r"((a)[1]), "r"((a)[2]), "r"((a)[3]), "r"(b0), "r"(b1))

// ---------------- prep kernels ----------------------------------------------
__global__ __launch_bounds__(256)
void convert_x_kernel(const float* __restrict__ x)
{
    size_t i = ((size_t)blockIdx.x * 256 + threadIdx.x) * 4;
    float4 v = *(const float4*)(x + i);
    __half h[4] = {__float2half(v.x), __float2half(v.y),
                   __float2half(v.z), __float2half(v.w)};
    *(uint2*)(g_xh + i) = *(uint2*)h;
}

// transpose: in fp32 [R][C] -> (device-global) fp16 [C][R]
__global__ __launch_bounds__(256)
void transpose_h_kernel(const float* __restrict__ in, int wsel, int R, int C)
{
    __half* __restrict__ oh = wsel ? g_Wot_h : g_Wint_h;

    __shared__ float tile[32][33];
    int tx = threadIdx.x, ty = threadIdx.y;
    int x = blockIdx.x * 32 + tx;
    int y0 = blockIdx.y * 32;
    #pragma unroll
    for (int j = ty; j < 32; j += 8)
        tile[j][tx] = in[(size_t)(y0 + j) * C + x];
    __syncthreads();
    int ox = y0 + tx;
    int oy0 = blockIdx.x * 32;
    #pragma unroll
    for (int j = ty; j < 32; j += 8)
        oh[(size_t)(oy0 + j) * R + ox] = __float2half(tile[tx][j]);
}

// ---------------- single-pass fp16 mma.sync GEMM -----------------------------
// gsel 0: C = g_BCx = g_xh @ g_Wint_h^T  (Cw = N3H)
// gsel 1: C = Cout  = g_yh @ g_Wot_h^T   (Cw = HH)
__global__ __launch_bounds__(256, 2)
void gemm_mma_kernel(int gsel, float* __restrict__ Cout)
{
    const __half* __restrict__ A = gsel ? g_yh : g_xh;
    const __half* __restrict__ B = gsel ? g_Wot_h : g_Wint_h;
    float* __restrict__ C  = gsel ? Cout : g_BCx;
    const int Cw = gsel ? HH : N3H;

    __shared__ __align__(1024) char smem[NSTAGE * STG_B];
    const int tid = threadIdx.x;
    const int wid = tid >> 5;
    const int lid = tid & 31;
    const int wm = wid & 3;           // 4 warps in M -> 32 rows each
    const int wn = wid >> 2;          // 2 warps in N -> 64 cols each
    const int bm = blockIdx.y * 128;
    const int bn = blockIdx.x * 128;

    float acc[2][8][4];
    #pragma unroll
    for (int t = 0; t < 2; ++t)
        #pragma unroll
        for (int j = 0; j < 8; ++j)
            #pragma unroll
            for (int e = 0; e < 4; ++e) acc[t][j][e] = 0.f;

    const int a_row = (lid & 15);
    const int a_kb  = (lid & 16) ? 16 : 0;
    const int b_row = (lid & 7) + ((lid & 16) ? 8 : 0);
    const int b_kb  = (lid & 8) ? 16 : 0;

    // loader: one stage = A tile + B tile, 128 rows x 4 chunks each -> 4/thread
    auto load_stage = [&](char* sbase, int k0) {
        #pragma unroll
        for (int j = 0; j < 4; ++j) {
            int c   = tid + j * 256;       // 0..1023
            int sub = c >> 9;              // 0 = A, 1 = B
            int cc  = c & 511;
            int r   = cc >> 2, ch = cc & 3;
            const int rowbase = sub ? bn : bm;
            const __half* src = (sub ? B : A)
                                + (size_t)(rowbase + r) * KDIM + k0 + ch * 8;
            uint32_t dst = smem_u32(sbase + sub * TILEB);
            CP_ASYNC16(dst + SWZ64(r * ROWB + ch * 16), src);
        }
        CP_ASYNC_COMMIT();
    };

    // prologue: 2 stages in flight
    load_stage(smem,         0);
    load_stage(smem + STG_B, 32);

    int cur = 0;
    for (int i = 0; i < NITER; ++i) {
        if (i + 1 < NITER) { CP_ASYNC_WAIT(1); } else { CP_ASYNC_WAIT(0); }
        __syncthreads();

        char* sbase = smem + cur * STG_B;
        const uint32_t tA = smem_u32(sbase);
        const uint32_t tB = tA + TILEB;

        #pragma unroll
        for (int kk = 0; kk < KCH; ++kk) {
            const int kb = kk * 32;
            uint32_t av[2][4], bv[4][4];
            #pragma unroll
            for (int t = 0; t < 2; ++t) {
                int row = wm * 32 + t * 16 + a_row;
                LDSM_X4(av[t][0], av[t][1], av[t][2], av[t][3],
                        tA + SWZ64(row * ROWB + kb + a_kb));
            }
            #pragma unroll
            for (int g = 0; g < 4; ++g) {
                int row = wn * 64 + g * 16 + b_row;
                LDSM_X4(bv[g][0], bv[g][1], bv[g][2], bv[g][3],
                        tB + SWZ64(row * ROWB + kb + b_kb));
            }
            #pragma unroll
            for (int t = 0; t < 2; ++t)
                #pragma unroll
                for (int g = 0; g < 4; ++g) {
                    MMA16816(acc[t][2 * g],     av[t], bv[g][0], bv[g][1]);
                    MMA16816(acc[t][2 * g + 1], av[t], bv[g][2], bv[g][3]);
                }
        }

        // load stage i+2 into (cur+2)%NSTAGE: its readers (iter i-1) passed
        // the barrier at the top of this iteration -> safe with one barrier.
        if (i + 2 < NITER) {
            int nxt = cur + 2; if (nxt >= NSTAGE) nxt -= NSTAGE;
            load_stage(smem + nxt * STG_B, (i + 2) * 32);
        }
        if (++cur == NSTAGE) cur = 0;
    }

    // epilogue: fp32 accum -> C (contiguous float2 stores)
    const int r0 = bm + wm * 32 + (lid >> 2);
    const int cb = bn + wn * 64 + (lid & 3) * 2;
    #pragma unroll
    for (int t = 0; t < 2; ++t)
        #pragma unroll
        for (int j = 0; j < 8; ++j) {
            float2 v0 = make_float2(acc[t][j][0], acc[t][j][1]);
            float2 v1 = make_float2(acc[t][j][2], acc[t][j][3]);
            *(float2*)(C + (size_t)(r0 + t * 16)     * Cw + cb + j * 8) = v0;
            *(float2*)(C + (size_t)(r0 + t * 16 + 8) * Cw + cb + j * 8) = v1;
        }
}

// ---------------- fused gate + mask + causal conv + Cg gate -----------------
// float2 per thread, 64-t chunks, restrict pointers, unroll for ILP.
#define CONV_CHUNK 64

__global__ __launch_bounds__(256)
void conv_kernel(const int* __restrict__ mask, const float* __restrict__ conv_w)
{
    const int h2 = (blockIdx.x * 256 + threadIdx.x) * 2;   // even h
    const int b  = blockIdx.z;
    const int t0 = blockIdx.y * CONV_CHUNK;

    const float* __restrict__ BC = g_BCx;
    __half*      __restrict__ Y  = g_yh;
    const int*   __restrict__ M  = mask + b * TT;

    float2 cw[LL];
    #pragma unroll
    for (int k = 0; k < LL; ++k) {
        cw[k].x = conv_w[h2 * LL + k];
        cw[k].y = conv_w[(h2 + 1) * LL + k];
    }

    float2 p1 = {0.f, 0.f}, p2 = {0.f, 0.f}, p3 = {0.f, 0.f};
    #pragma unroll
    for (int d = 3; d >= 1; --d) {
        int t = t0 - d;
        float2 bx = {0.f, 0.f};
        if (t >= 0 && M[t] != 0) {
            size_t base = ((size_t)(b * TT + t)) * N3H;
            float2 Bg = *(const float2*)(BC + base + h2);
            float2 xg = *(const float2*)(BC + base + 2 * HH + h2);
            bx.x = Bg.x * xg.x; bx.y = Bg.y * xg.y;
        }
        p3 = p2; p2 = p1; p1 = bx;
    }

    #pragma unroll 2
    for (int t = t0; t < t0 + CONV_CHUNK; ++t) {
        size_t base = ((size_t)(b * TT + t)) * N3H;
        float2 Bg = *(const float2*)(BC + base + h2);
        float2 Cg = *(const float2*)(BC + base + HH + h2);
        float2 xg = *(const float2*)(BC + base + 2 * HH + h2);
        bool m = (M[t] != 0);
        float2 bx;
        bx.x = m ? (Bg.x * xg.x) : 0.f;
        bx.y = m ? (Bg.y * xg.y) : 0.f;
        float2 conv;
        conv.x = cw[0].x * p3.x + cw[1].x * p2.x + cw[2].x * p1.x + cw[3].x * bx.x;
        conv.y = cw[0].y * p3.y + cw[1].y * p2.y + cw[2].y * p1.y + cw[3].y * bx.y;
        *(__half2*)(Y + ((size_t)(b * TT + t)) * HH + h2) =
            __floats2half2_rn(Cg.x * conv.x, Cg.y * conv.y);
        p3 = p2; p2 = p1; p1 = bx;
    }
}

// ---------------- launch -----------------------------------------------------
extern "C" void kernel_launch(void* const* d_in, const int* in_sizes, int n_in,
                              void* d_out, int out_size)
{
    const float* x      = (const float*)d_in[0];
    const int*   mask   = (const int*)d_in[1];    // bool widened to int32
    const float* W_in   = (const float*)d_in[2];
    const float* conv_w = (const float*)d_in[3];
    const float* W_out  = (const float*)d_in[4];
    float*       out    = (float*)d_out;

    // prep: convert x to fp16, transpose weights to fp16
    convert_x_kernel<<<(size_t)MROWS * HH / (256 * 4), 256>>>(x);
    transpose_h_kernel<<<dim3(N3H / 32, HH / 32), dim3(32, 8)>>>(W_in, 0, HH, N3H);
    transpose_h_kernel<<<dim3(HH / 32, HH / 32), dim3(32, 8)>>>(W_out, 1, HH, HH);

    // GEMM1: BCx = x @ W_in   (16384x2048 @ 2048x6144)
    gemm_mma_kernel<<<dim3(N3H / 128, MROWS / 128), 256>>>(0, nullptr);

    // gate + conv + gate -> y (fp16)
    conv_kernel<<<dim3(HH / 512, TT / CONV_CHUNK, BB), 256>>>(mask, conv_w);

    // GEMM2: out = y @ W_out  (16384x2048 @ 2048x2048)
    gemm_mma_kernel<<<dim3(HH / 128, MROWS / 128), 256>>>(1, out);
}

// round 16
// speedup vs baseline: 1.0540x; 1.0060x over previous
#include <cuda_runtime.h>
#include <cuda_fp16.h>
#include <cstdint>

// Problem dims (fixed)
#define BB 4
#define TT 4096
#define HH 2048
#define LL 4
#define MROWS 16384
#define N3H 6144
#define KDIM 2048

// GEMM tiling: CTA 128x128, BK=32, 3-stage cp.async, 8 warps (4x2),
// warp 32x64, single pass (A fp16 K-major, B fp16 K-major + ldmatrix.trans).
#define KCH   2
#define NITER (KDIM / 32)             // 64
#define TILEB 8192                    // A: 128r x 64B ; B: 32r x 256B (both 8 KB)
#define STG_B (2 * TILEB)             // 16 KB
#define NSTAGE 3                      // 48 KB static

// ---------------- scratch (__device__ globals; referenced ONLY in device code)
__device__ float  g_BCx[(size_t)MROWS * N3H];     // 384 MB fp32
__device__ __half g_xh[(size_t)MROWS * HH];
__device__ __half g_yh[(size_t)MROWS * HH];
__device__ __half g_Wi16[(size_t)HH * N3H];       // W_in  [2048][6144] fp16 (K-major)
__device__ __half g_Wo16[(size_t)HH * HH];        // W_out [2048][2048] fp16 (K-major)

// ---------------- PTX helpers (plain sm_103-safe) ----------------------------
__device__ __forceinline__ uint32_t smem_u32(const void* p) {
    uint32_t a;
    asm("{ .reg .u64 t; cvta.to.shared.u64 t, %1; cvt.u32.u64 %0, t; }" : "=r"(a) : "l"(p));
    return a;
}
// A tiles: 64B rows -> conflict-free for 8-row ldmatrix groups
#define SWZ64(off)  ((off) ^ (((off) >> 3) & 0x30))
// B tiles: 256B rows -> spread k-rows across 16B slots
#define SWZ256(off) ((off) ^ (((off) >> 4) & 0x70))

#define CP_ASYNC16(dst, src) \
    asm volatile("cp.async.cg.shared.global [%0], [%1], 16;" :: "r"(dst), "l"(src))
#define CP_ASYNC_COMMIT() asm volatile("cp.async.commit_group;")
#define CP_ASYNC_WAIT(n)  asm volatile("cp.async.wait_group %0;" :: "n"(n))

#define LDSM_X4(r0, r1, r2, r3, addr) \
    asm volatile("ldmatrix.sync.aligned.m8n8.x4.shared.b16 {%0,%1,%2,%3}, [%4];" \
        : "=r"(r0), "=r"(r1), "=r"(r2), "=r"(r3) : "r"(addr))
#define LDSM_X4_T(r0, r1, r2, r3, addr) \
    asm volatile("ldmatrix.sync.aligned.m8n8.x4.trans.shared.b16 {%0,%1,%2,%3}, [%4];" \
        : "=r"(r0), "=r"(r1), "=r"(r2), "=r"(r3) : "r"(addr))

// NOT volatile: pure register computation; ptxas may schedule freely.
#define MMA16816(d, a, b0, b1) \
    asm("mma.sync.aligned.m16n8k16.row.col.f32.f16.f16.f32 " \
        "{%0,%1,%2,%3}, {%4,%5,%6,%7}, {%8,%9}, {%0,%1,%2,%3};" \
        : "+f"((d)[0]), "+f"((d)[1]), "+f"((d)[2]), "+f"((d)[3]) \
        : "r"((a)[0]), "r"((a)[1]), "r"((a)[2]), "r"((a)[3]), "r"(b0), "r"(b1))

// ---------------- prep kernels ----------------------------------------------
__global__ __launch_bounds__(256)
void convert_x_kernel(const float* __restrict__ x)
{
    size_t i = ((size_t)blockIdx.x * 256 + threadIdx.x) * 4;
    float4 v = *(const float4*)(x + i);
    __half h[4] = {__float2half(v.x), __float2half(v.y),
                   __float2half(v.z), __float2half(v.w)};
    *(uint2*)(g_xh + i) = *(uint2*)h;
}

// elementwise fp32 -> fp16 (layout preserved); wsel: 0 -> g_Wi16, 1 -> g_Wo16
__global__ __launch_bounds__(256)
void convert_w_kernel(const float* __restrict__ in, int wsel)
{
    __half* __restrict__ o = wsel ? g_Wo16 : g_Wi16;
    size_t i = ((size_t)blockIdx.x * 256 + threadIdx.x) * 4;
    float4 v = *(const float4*)(in + i);
    __half h[4] = {__float2half(v.x), __float2half(v.y),
                   __float2half(v.z), __float2half(v.w)};
    *(uint2*)(o + i) = *(uint2*)h;
}

// ---------------- single-pass fp16 mma.sync GEMM -----------------------------
// A [M][K] K-major fp16; B [K][N] K-major fp16 (ldmatrix.trans).
// gsel 0: C = g_BCx = g_xh @ g_Wi16  (Cw = N3H)
// gsel 1: C = Cout  = g_yh @ g_Wo16  (Cw = HH)
__global__ __launch_bounds__(256, 2)
void gemm_mma_kernel(int gsel, float* __restrict__ Cout)
{
    const __half* __restrict__ A = gsel ? g_yh : g_xh;
    const __half* __restrict__ B = gsel ? g_Wo16 : g_Wi16;
    float* __restrict__ C  = gsel ? Cout : g_BCx;
    const int Cw = gsel ? HH : N3H;     // also B row stride

    __shared__ __align__(1024) char smem[NSTAGE * STG_B];
    const int tid = threadIdx.x;
    const int wid = tid >> 5;
    const int lid = tid & 31;
    const int wm = wid & 3;           // 4 warps in M -> 32 rows each
    const int wn = wid >> 2;          // 2 warps in N -> 64 cols each
    const int bm = blockIdx.y * 128;
    const int bn = blockIdx.x * 128;

    float acc[2][8][4];
    #pragma unroll
    for (int t = 0; t < 2; ++t)
        #pragma unroll
        for (int j = 0; j < 8; ++j)
            #pragma unroll
            for (int e = 0; e < 4; ++e) acc[t][j][e] = 0.f;

    // A ldmatrix lane address components
    const int a_row = (lid & 15);
    const int a_kb  = (lid & 16) ? 16 : 0;
    // B ldmatrix.trans lane address components:
    // matrix sel: 0=(k0..8,n0..8) 1=(k8..16,n0..8) 2=(k0..8,n8..16) 3=(k8..16,n8..16)
    const int bsel  = lid >> 3;
    const int b_kin = (bsel & 1) * 8 + (lid & 7);   // k within 16-row group
    const int b_nin = (bsel >> 1) * 8;              // n within 16-col group

    // loader: A tile 128 rows x 4 chunks, B tile 32 rows x 16 chunks -> 4/thread
    auto load_stage = [&](char* sbase, int k0) {
        #pragma unroll
        for (int j = 0; j < 4; ++j) {
            int c = tid + j * 256;             // 0..1023
            if (c < 512) {                     // A chunks
                int r = c >> 2, ch = c & 3;
                const __half* src = A + (size_t)(bm + r) * KDIM + k0 + ch * 8;
                uint32_t dst = smem_u32(sbase);
                CP_ASYNC16(dst + SWZ64(r * 64 + ch * 16), src);
            } else {                           // B chunks (K-major rows)
                int cc = c - 512;
                int r = cc >> 4, ch = cc & 15; // r = k row 0..31, ch = 16B chunk
                const __half* src = B + (size_t)(k0 + r) * Cw + bn + ch * 8;
                uint32_t dst = smem_u32(sbase + TILEB);
                CP_ASYNC16(dst + SWZ256(r * 256 + ch * 16), src);
            }
        }
        CP_ASYNC_COMMIT();
    };

    // prologue: 2 stages in flight
    load_stage(smem,         0);
    load_stage(smem + STG_B, 32);

    int cur = 0;
    for (int i = 0; i < NITER; ++i) {
        if (i + 1 < NITER) { CP_ASYNC_WAIT(1); } else { CP_ASYNC_WAIT(0); }
        __syncthreads();

        char* sbase = smem + cur * STG_B;
        const uint32_t tA = smem_u32(sbase);
        const uint32_t tB = tA + TILEB;

        #pragma unroll
        for (int kk = 0; kk < KCH; ++kk) {
            uint32_t av[2][4], bv[4][4];
            #pragma unroll
            for (int t = 0; t < 2; ++t) {
                int row = wm * 32 + t * 16 + a_row;
                LDSM_X4(av[t][0], av[t][1], av[t][2], av[t][3],
                        tA + SWZ64(row * 64 + kk * 32 + a_kb));
            }
            #pragma unroll
            for (int g = 0; g < 4; ++g) {
                int krow = kk * 16 + b_kin;
                int ncol = wn * 64 + g * 16 + b_nin;
                LDSM_X4_T(bv[g][0], bv[g][1], bv[g][2], bv[g][3],
                          tB + SWZ256(krow * 256 + ncol * 2));
            }
            #pragma unroll
            for (int t = 0; t < 2; ++t)
                #pragma unroll
                for (int g = 0; g < 4; ++g) {
                    MMA16816(acc[t][2 * g],     av[t], bv[g][0], bv[g][1]);
                    MMA16816(acc[t][2 * g + 1], av[t], bv[g][2], bv[g][3]);
                }
        }

        // load stage i+2 into (cur+2)%NSTAGE: its readers (iter i-1) passed
        // the barrier at the top of this iteration -> safe with one barrier.
        if (i + 2 < NITER) {
            int nxt = cur + 2; if (nxt >= NSTAGE) nxt -= NSTAGE;
            load_stage(smem + nxt * STG_B, (i + 2) * 32);
        }
        if (++cur == NSTAGE) cur = 0;
    }

    // epilogue: fp32 accum -> C (contiguous float2 stores)
    const int r0 = bm + wm * 32 + (lid >> 2);
    const int cb = bn + wn * 64 + (lid & 3) * 2;
    #pragma unroll
    for (int t = 0; t < 2; ++t)
        #pragma unroll
        for (int j = 0; j < 8; ++j) {
            float2 v0 = make_float2(acc[t][j][0], acc[t][j][1]);
            float2 v1 = make_float2(acc[t][j][2], acc[t][j][3]);
            *(float2*)(C + (size_t)(r0 + t * 16)     * Cw + cb + j * 8) = v0;
            *(float2*)(C + (size_t)(r0 + t * 16 + 8) * Cw + cb + j * 8) = v1;
        }
}

// ---------------- fused gate + mask + causal conv + Cg gate -----------------
// float2 per thread, 64-t chunks, restrict pointers, unroll for ILP.
#define CONV_CHUNK 64

__global__ __launch_bounds__(256)
void conv_kernel(const int* __restrict__ mask, const float* __restrict__ conv_w)
{
    const int h2 = (blockIdx.x * 256 + threadIdx.x) * 2;   // even h
    const int b  = blockIdx.z;
    const int t0 = blockIdx.y * CONV_CHUNK;

    const float* __restrict__ BC = g_BCx;
    __half*      __restrict__ Y  = g_yh;
    const int*   __restrict__ M  = mask + b * TT;

    float2 cw[LL];
    #pragma unroll
    for (int k = 0; k < LL; ++k) {
        cw[k].x = conv_w[h2 * LL + k];
        cw[k].y = conv_w[(h2 + 1) * LL + k];
    }

    float2 p1 = {0.f, 0.f}, p2 = {0.f, 0.f}, p3 = {0.f, 0.f};
    #pragma unroll
    for (int d = 3; d >= 1; --d) {
        int t = t0 - d;
        float2 bx = {0.f, 0.f};
        if (t >= 0 && M[t] != 0) {
            size_t base = ((size_t)(b * TT + t)) * N3H;
            float2 Bg = *(const float2*)(BC + base + h2);
            float2 xg = *(const float2*)(BC + base + 2 * HH + h2);
            bx.x = Bg.x * xg.x; bx.y = Bg.y * xg.y;
        }
        p3 = p2; p2 = p1; p1 = bx;
    }

    #pragma unroll 2
    for (int t = t0; t < t0 + CONV_CHUNK; ++t) {
        size_t base = ((size_t)(b * TT + t)) * N3H;
        float2 Bg = *(const float2*)(BC + base + h2);
        float2 Cg = *(const float2*)(BC + base + HH + h2);
        float2 xg = *(const float2*)(BC + base + 2 * HH + h2);
        bool m = (M[t] != 0);
        float2 bx;
        bx.x = m ? (Bg.x * xg.x) : 0.f;
        bx.y = m ? (Bg.y * xg.y) : 0.f;
        float2 conv;
        conv.x = cw[0].x * p3.x + cw[1].x * p2.x + cw[2].x * p1.x + cw[3].x * bx.x;
        conv.y = cw[0].y * p3.y + cw[1].y * p2.y + cw[2].y * p1.y + cw[3].y * bx.y;
        *(__half2*)(Y + ((size_t)(b * TT + t)) * HH + h2) =
            __floats2half2_rn(Cg.x * conv.x, Cg.y * conv.y);
        p3 = p2; p2 = p1; p1 = bx;
    }
}

// ---------------- launch -----------------------------------------------------
extern "C" void kernel_launch(void* const* d_in, const int* in_sizes, int n_in,
                              void* d_out, int out_size)
{
    const float* x      = (const float*)d_in[0];
    const int*   mask   = (const int*)d_in[1];    // bool widened to int32
    const float* W_in   = (const float*)d_in[2];
    const float* conv_w = (const float*)d_in[3];
    const float* W_out  = (const float*)d_in[4];
    float*       out    = (float*)d_out;

    // prep: elementwise fp32 -> fp16 (no transposes needed; B stays K-major)
    convert_x_kernel<<<(size_t)MROWS * HH / (256 * 4), 256>>>(x);
    convert_w_kernel<<<(size_t)HH * N3H / (256 * 4), 256>>>(W_in, 0);
    convert_w_kernel<<<(size_t)HH * HH / (256 * 4), 256>>>(W_out, 1);

    // GEMM1: BCx = x @ W_in   (16384x2048 @ 2048x6144)
    gemm_mma_kernel<<<dim3(N3H / 128, MROWS / 128), 256>>>(0, nullptr);

    // gate + conv + gate -> y (fp16)
    conv_kernel<<<dim3(HH / 512, TT / CONV_CHUNK, BB), 256>>>(mask, conv_w);

    // GEMM2: out = y @ W_out  (16384x2048 @ 2048x2048)
    gemm_mma_kernel<<<dim3(HH / 128, MROWS / 128), 256>>>(1, out);
}